// round 1
// baseline (speedup 1.0000x reference)
#include <cuda_runtime.h>
#include <math.h>

// ---------------- problem constants ----------------
#define MROWS   8192        // B*S
#define DMODEL  1024
#define NHEAD   16
#define DHEAD   64
#define SEQ     2048
#define CTXROWS 308         // B*77
#define CTXLEN  77
#define CTXDIM  768
#define FFH     8192
#define FFHALF  4096

// ---------------- scratch (static device globals; no runtime alloc) ----------------
__device__ float g_xn[MROWS * DMODEL];
__device__ float g_q [MROWS * DMODEL];
__device__ float g_k [MROWS * DMODEL];
__device__ float g_v [MROWS * DMODEL];
__device__ float g_o [MROWS * DMODEL];
__device__ float g_xa[MROWS * DMODEL];
__device__ float g_h [(size_t)MROWS * FFH];
__device__ float g_gl[(size_t)MROWS * FFHALF];

// ---------------- LayerNorm: one block (256 thr) per row of 1024 ----------------
__global__ __launch_bounds__(256) void ln_kernel(const float* __restrict__ X,
                                                 const float* __restrict__ gma,
                                                 const float* __restrict__ bta,
                                                 float* __restrict__ Y) {
    int row = blockIdx.x;
    int tid = threadIdx.x;
    const float4* xr = (const float4*)(X + (size_t)row * DMODEL);
    float4 x4 = xr[tid];
    float s  = x4.x + x4.y + x4.z + x4.w;
    float ss = x4.x*x4.x + x4.y*x4.y + x4.z*x4.z + x4.w*x4.w;
#pragma unroll
    for (int off = 16; off > 0; off >>= 1) {
        s  += __shfl_xor_sync(0xffffffffu, s,  off);
        ss += __shfl_xor_sync(0xffffffffu, ss, off);
    }
    __shared__ float red[16];
    int lane = tid & 31, wid = tid >> 5;
    if (lane == 0) { red[wid] = s; red[8 + wid] = ss; }
    __syncthreads();
    float tot = 0.f, tot2 = 0.f;
#pragma unroll
    for (int i = 0; i < 8; i++) { tot += red[i]; tot2 += red[8 + i]; }
    const float inv = 1.0f / (float)DMODEL;
    float mu  = tot * inv;
    float var = tot2 * inv - mu * mu;
    float rs  = rsqrtf(var + 1e-5f);
    float4 gv = ((const float4*)gma)[tid];
    float4 bv = ((const float4*)bta)[tid];
    float4 o4;
    o4.x = (x4.x - mu) * rs * gv.x + bv.x;
    o4.y = (x4.y - mu) * rs * gv.y + bv.y;
    o4.z = (x4.z - mu) * rs * gv.z + bv.z;
    o4.w = (x4.w - mu) * rs * gv.w + bv.w;
    ((float4*)(Y + (size_t)row * DMODEL))[tid] = o4;
}

// ---------------- fp32 GEMM: C[M,N] = A[M,K] @ B[K,N] (+bias)(+resid) ----------------
// BM=BN=128, BK=16, 256 threads, 8x8 per thread (cols split tx*4 and 64+tx*4).
__global__ __launch_bounds__(256) void gemm_kernel(const float* __restrict__ A,
                                                   const float* __restrict__ B,
                                                   float* __restrict__ C,
                                                   int M, int N, int K,
                                                   const float* __restrict__ bias,
                                                   const float* __restrict__ resid) {
    __shared__ float As[16][128];
    __shared__ float Bs[16][128];
    int tid = threadIdx.x;
    int tx = tid & 15, ty = tid >> 4;
    int row0 = blockIdx.y * 128, col0 = blockIdx.x * 128;
    float acc[8][8];
#pragma unroll
    for (int i = 0; i < 8; i++)
#pragma unroll
        for (int j = 0; j < 8; j++) acc[i][j] = 0.f;

    for (int k0 = 0; k0 < K; k0 += 16) {
#pragma unroll
        for (int i = 0; i < 2; i++) {
            int idx = tid * 2 + i;
            int r = idx >> 2, kc = idx & 3;
            int gr = row0 + r;
            float4 f = make_float4(0.f, 0.f, 0.f, 0.f);
            if (gr < M) f = *(const float4*)(A + (size_t)gr * K + k0 + kc * 4);
            As[kc * 4 + 0][r] = f.x;
            As[kc * 4 + 1][r] = f.y;
            As[kc * 4 + 2][r] = f.z;
            As[kc * 4 + 3][r] = f.w;
        }
#pragma unroll
        for (int i = 0; i < 2; i++) {
            int idx = tid * 2 + i;
            int kb = idx >> 5, nc = idx & 31;
            float4 f = *(const float4*)(B + (size_t)(k0 + kb) * N + col0 + nc * 4);
            *(float4*)&Bs[kb][nc * 4] = f;
        }
        __syncthreads();
#pragma unroll
        for (int kk = 0; kk < 16; kk++) {
            float a[8], bb[8];
            *(float4*)&a[0]  = *(float4*)&As[kk][ty * 8];
            *(float4*)&a[4]  = *(float4*)&As[kk][ty * 8 + 4];
            *(float4*)&bb[0] = *(float4*)&Bs[kk][tx * 4];
            *(float4*)&bb[4] = *(float4*)&Bs[kk][64 + tx * 4];
#pragma unroll
            for (int i = 0; i < 8; i++)
#pragma unroll
                for (int j = 0; j < 8; j++) acc[i][j] += a[i] * bb[j];
        }
        __syncthreads();
    }
    // epilogue
#pragma unroll
    for (int i = 0; i < 8; i++) {
        int gr = row0 + ty * 8 + i;
        if (gr >= M) continue;
#pragma unroll
        for (int half = 0; half < 2; half++) {
            int gc = col0 + half * 64 + tx * 4;
            float4 r4;
            r4.x = acc[i][half * 4 + 0];
            r4.y = acc[i][half * 4 + 1];
            r4.z = acc[i][half * 4 + 2];
            r4.w = acc[i][half * 4 + 3];
            if (bias) {
                float4 b4 = *(const float4*)(bias + gc);
                r4.x += b4.x; r4.y += b4.y; r4.z += b4.z; r4.w += b4.w;
            }
            if (resid) {
                float4 q4 = *(const float4*)(resid + (size_t)gr * N + gc);
                r4.x += q4.x; r4.y += q4.y; r4.z += q4.z; r4.w += q4.w;
            }
            *(float4*)(C + (size_t)gr * N + gc) = r4;
        }
    }
}

// ---------------- flash attention: 64-query tile per block ----------------
// grid (qlen/64, NHEAD, B), 256 threads, 4x4 micro-tile (16x16 thread grid)
#define ATTN_SMEM_FLOATS (4096 + 64 * 68 + 4096 + 4096)
__global__ __launch_bounds__(256) void attn_kernel(const float* __restrict__ Q,
                                                   const float* __restrict__ Kp,
                                                   const float* __restrict__ V,
                                                   float* __restrict__ O,
                                                   int qlen, int kvlen) {
    extern __shared__ float sm[];
    float (*qs)[64] = (float(*)[64])sm;                 // 64x64
    float (*ks)[68] = (float(*)[68])(sm + 4096);        // 64x68 (pad for conflict-free col reads)
    float (*vs)[64] = (float(*)[64])(sm + 4096 + 64 * 68);
    float (*ps)[64] = (float(*)[64])(sm + 4096 + 64 * 68 + 4096);

    int b = blockIdx.z, h = blockIdx.y, qt = blockIdx.x;
    int tid = threadIdx.x;
    int tx = tid & 15, ty = tid >> 4;

    const size_t qoff = ((size_t)(b * qlen) + qt * 64) * DMODEL + h * DHEAD;
    // load 64x64 q tile (1024 float4 / 256 thr = 4 each)
#pragma unroll
    for (int i = 0; i < 4; i++) {
        int idx = tid + i * 256;
        int r = idx >> 4, c = (idx & 15) * 4;
        *(float4*)&qs[r][c] = *(const float4*)(Q + qoff + (size_t)r * DMODEL + c);
    }

    float m_[4], l_[4], oacc[4][4];
#pragma unroll
    for (int i = 0; i < 4; i++) {
        m_[i] = -1e30f; l_[i] = 0.f;
#pragma unroll
        for (int j = 0; j < 4; j++) oacc[i][j] = 0.f;
    }

    int ntiles = (kvlen + 63) >> 6;
    for (int kt = 0; kt < ntiles; kt++) {
#pragma unroll
        for (int i = 0; i < 4; i++) {
            int idx = tid + i * 256;
            int r = idx >> 4, c = (idx & 15) * 4;
            int kr = kt * 64 + r;
            float4 kf = make_float4(0.f, 0.f, 0.f, 0.f), vf = kf;
            if (kr < kvlen) {
                size_t off = ((size_t)(b * kvlen + kr)) * DMODEL + h * DHEAD + c;
                kf = *(const float4*)(Kp + off);
                vf = *(const float4*)(V + off);
            }
            *(float4*)&ks[r][c] = kf;
            *(float4*)&vs[r][c] = vf;
        }
        __syncthreads();

        float s[4][4];
#pragma unroll
        for (int i = 0; i < 4; i++)
#pragma unroll
            for (int j = 0; j < 4; j++) s[i][j] = 0.f;

#pragma unroll
        for (int dd = 0; dd < 64; dd += 4) {
            float4 qa[4], kb4[4];
#pragma unroll
            for (int i = 0; i < 4; i++) qa[i]  = *(float4*)&qs[ty * 4 + i][dd];
#pragma unroll
            for (int j = 0; j < 4; j++) kb4[j] = *(float4*)&ks[tx * 4 + j][dd];
#pragma unroll
            for (int i = 0; i < 4; i++)
#pragma unroll
                for (int j = 0; j < 4; j++)
                    s[i][j] += qa[i].x * kb4[j].x + qa[i].y * kb4[j].y +
                               qa[i].z * kb4[j].z + qa[i].w * kb4[j].w;
        }
        // scale + mask
#pragma unroll
        for (int i = 0; i < 4; i++)
#pragma unroll
            for (int j = 0; j < 4; j++) {
                int kc = kt * 64 + tx * 4 + j;
                s[i][j] = (kc < kvlen) ? s[i][j] * 0.125f : -1e30f;
            }
        // online softmax (row groups of 16 lanes)
#pragma unroll
        for (int i = 0; i < 4; i++) {
            float mloc = fmaxf(fmaxf(s[i][0], s[i][1]), fmaxf(s[i][2], s[i][3]));
#pragma unroll
            for (int off = 1; off < 16; off <<= 1)
                mloc = fmaxf(mloc, __shfl_xor_sync(0xffffffffu, mloc, off));
            float mnew  = fmaxf(m_[i], mloc);
            float alpha = __expf(m_[i] - mnew);
            float p0 = __expf(s[i][0] - mnew);
            float p1 = __expf(s[i][1] - mnew);
            float p2 = __expf(s[i][2] - mnew);
            float p3 = __expf(s[i][3] - mnew);
            float psum = p0 + p1 + p2 + p3;
#pragma unroll
            for (int off = 1; off < 16; off <<= 1)
                psum += __shfl_xor_sync(0xffffffffu, psum, off);
            l_[i] = l_[i] * alpha + psum;
            m_[i] = mnew;
#pragma unroll
            for (int j = 0; j < 4; j++) oacc[i][j] *= alpha;
            float4 pv = make_float4(p0, p1, p2, p3);
            *(float4*)&ps[ty * 4 + i][tx * 4] = pv;
        }
        __syncthreads();
        // O += P @ V
#pragma unroll
        for (int kk = 0; kk < 64; kk += 4) {
            float4 vr0 = *(float4*)&vs[kk + 0][tx * 4];
            float4 vr1 = *(float4*)&vs[kk + 1][tx * 4];
            float4 vr2 = *(float4*)&vs[kk + 2][tx * 4];
            float4 vr3 = *(float4*)&vs[kk + 3][tx * 4];
#pragma unroll
            for (int i = 0; i < 4; i++) {
                float4 pa = *(float4*)&ps[ty * 4 + i][kk];
                oacc[i][0] += pa.x * vr0.x + pa.y * vr1.x + pa.z * vr2.x + pa.w * vr3.x;
                oacc[i][1] += pa.x * vr0.y + pa.y * vr1.y + pa.z * vr2.y + pa.w * vr3.y;
                oacc[i][2] += pa.x * vr0.z + pa.y * vr1.z + pa.z * vr2.z + pa.w * vr3.z;
                oacc[i][3] += pa.x * vr0.w + pa.y * vr1.w + pa.z * vr2.w + pa.w * vr3.w;
            }
        }
        __syncthreads();
    }
    // normalize + store
#pragma unroll
    for (int i = 0; i < 4; i++) {
        float inv = 1.0f / l_[i];
        float4 o4 = make_float4(oacc[i][0] * inv, oacc[i][1] * inv,
                                oacc[i][2] * inv, oacc[i][3] * inv);
        int r = ty * 4 + i;
        *(float4*)(O + qoff + (size_t)r * DMODEL + tx * 4) = o4;
    }
}

// ---------------- GeGLU pointwise: out = u * gelu_exact(gate) ----------------
__global__ __launch_bounds__(256) void geglu_kernel(const float* __restrict__ Hb,
                                                    float* __restrict__ Gb) {
    int row = blockIdx.y;
    int c = (blockIdx.x * 256 + threadIdx.x) * 4;
    const float* hr = Hb + (size_t)row * FFH;
    float4 u = *(const float4*)(hr + c);
    float4 g = *(const float4*)(hr + FFHALF + c);
    const float k = 0.70710678118654752f;
    float4 r;
    r.x = u.x * (0.5f * g.x * (1.f + erff(g.x * k)));
    r.y = u.y * (0.5f * g.y * (1.f + erff(g.y * k)));
    r.z = u.z * (0.5f * g.z * (1.f + erff(g.z * k)));
    r.w = u.w * (0.5f * g.w * (1.f + erff(g.w * k)));
    *(float4*)(Gb + (size_t)row * FFHALF + c) = r;
}

// ---------------- launch ----------------
extern "C" void kernel_launch(void* const* d_in, const int* in_sizes, int n_in,
                              void* d_out, int out_size) {
    const float* x    = (const float*)d_in[0];
    const float* ctx  = (const float*)d_in[1];
    const float* ln1g = (const float*)d_in[2];
    const float* ln1b = (const float*)d_in[3];
    const float* ln2g = (const float*)d_in[4];
    const float* ln2b = (const float*)d_in[5];
    const float* ln3g = (const float*)d_in[6];
    const float* ln3b = (const float*)d_in[7];
    const float* a1wq = (const float*)d_in[8];
    const float* a1wk = (const float*)d_in[9];
    const float* a1wv = (const float*)d_in[10];
    const float* a1wo = (const float*)d_in[11];
    const float* a1bo = (const float*)d_in[12];
    const float* a2wq = (const float*)d_in[13];
    const float* a2wk = (const float*)d_in[14];
    const float* a2wv = (const float*)d_in[15];
    const float* a2wo = (const float*)d_in[16];
    const float* a2bo = (const float*)d_in[17];
    const float* ffw1 = (const float*)d_in[18];
    const float* ffb1 = (const float*)d_in[19];
    const float* ffw2 = (const float*)d_in[20];
    const float* ffb2 = (const float*)d_in[21];
    float* out = (float*)d_out;

    float *xn, *q, *k, *v, *o, *xa, *h, *gl;
    cudaGetSymbolAddress((void**)&xn, g_xn);
    cudaGetSymbolAddress((void**)&q,  g_q);
    cudaGetSymbolAddress((void**)&k,  g_k);
    cudaGetSymbolAddress((void**)&v,  g_v);
    cudaGetSymbolAddress((void**)&o,  g_o);
    cudaGetSymbolAddress((void**)&xa, g_xa);
    cudaGetSymbolAddress((void**)&h,  g_h);
    cudaGetSymbolAddress((void**)&gl, g_gl);

    const int attn_smem = ATTN_SMEM_FLOATS * 4;  // 66560 B
    cudaFuncSetAttribute(attn_kernel, cudaFuncAttributeMaxDynamicSharedMemorySize, attn_smem);

    dim3 blk(256);
    dim3 gemm1024(DMODEL / 128, MROWS / 128);       // (8, 64)
    dim3 gemmCtx(DMODEL / 128, (CTXROWS + 127) / 128);  // (8, 3)
    dim3 gemmFF1(FFH / 128, MROWS / 128);           // (64, 64)
    dim3 attng(SEQ / 64, NHEAD, 4);

    // --- self attention ---
    ln_kernel<<<MROWS, blk>>>(x, ln1g, ln1b, xn);
    gemm_kernel<<<gemm1024, blk>>>(xn, a1wq, q, MROWS, DMODEL, DMODEL, nullptr, nullptr);
    gemm_kernel<<<gemm1024, blk>>>(xn, a1wk, k, MROWS, DMODEL, DMODEL, nullptr, nullptr);
    gemm_kernel<<<gemm1024, blk>>>(xn, a1wv, v, MROWS, DMODEL, DMODEL, nullptr, nullptr);
    attn_kernel<<<attng, blk, attn_smem>>>(q, k, v, o, SEQ, SEQ);
    gemm_kernel<<<gemm1024, blk>>>(o, a1wo, xa, MROWS, DMODEL, DMODEL, a1bo, x);

    // --- cross attention ---
    ln_kernel<<<MROWS, blk>>>(xa, ln2g, ln2b, xn);
    gemm_kernel<<<gemm1024, blk>>>(xn, a2wq, q, MROWS, DMODEL, DMODEL, nullptr, nullptr);
    gemm_kernel<<<gemmCtx, blk>>>(ctx, a2wk, k, CTXROWS, DMODEL, CTXDIM, nullptr, nullptr);
    gemm_kernel<<<gemmCtx, blk>>>(ctx, a2wv, v, CTXROWS, DMODEL, CTXDIM, nullptr, nullptr);
    attn_kernel<<<attng, blk, attn_smem>>>(q, k, v, o, SEQ, CTXLEN);
    gemm_kernel<<<gemm1024, blk>>>(o, a2wo, xa, MROWS, DMODEL, DMODEL, a2bo, xa);

    // --- GeGLU feed-forward ---
    ln_kernel<<<MROWS, blk>>>(xa, ln3g, ln3b, xn);
    gemm_kernel<<<gemmFF1, blk>>>(xn, ffw1, h, MROWS, FFH, DMODEL, ffb1, nullptr);
    geglu_kernel<<<dim3(FFHALF / 1024, MROWS), blk>>>(h, gl);
    gemm_kernel<<<gemm1024, blk>>>(gl, ffw2, out, MROWS, DMODEL, FFHALF, ffb2, xa);
}

// round 4
// speedup vs baseline: 1.6699x; 1.6699x over previous
#include <cuda_runtime.h>
#include <cuda_bf16.h>
#include <math.h>
#include <cstdint>

// ---------------- problem constants ----------------
#define MROWS   8192        // B*S
#define DMODEL  1024
#define NHEAD   16
#define DHEAD   64
#define SEQ     2048
#define CTXROWS 308         // B*77
#define CTXLEN  77
#define CTXDIM  768
#define FFH     8192
#define FFHALF  4096

// ---------------- scratch (static device globals; no runtime alloc) ----------------
__device__ float g_q [MROWS * DMODEL];
__device__ float g_k [MROWS * DMODEL];
__device__ float g_v [MROWS * DMODEL];
__device__ float g_o [MROWS * DMODEL];
__device__ float g_xa[MROWS * DMODEL];
__device__ float g_h [(size_t)MROWS * FFH];
__device__ __nv_bfloat16 g_ah[(size_t)MROWS * FFHALF];   // activation hi
__device__ __nv_bfloat16 g_al[(size_t)MROWS * FFHALF];   // activation lo
__device__ __nv_bfloat16 g_bh[(size_t)FFH * DMODEL];     // weight hi (transposed [N,K])
__device__ __nv_bfloat16 g_bl[(size_t)FFH * DMODEL];     // weight lo

// ---------------- PTX helpers ----------------
__device__ __forceinline__ uint32_t smem_to_u32(const void* p) {
    uint32_t a;
    asm("{ .reg .u64 t; cvta.to.shared.u64 t, %1; cvt.u32.u64 %0, t; }" : "=r"(a) : "l"(p));
    return a;
}
#define CP_ASYNC16(dst, src) \
    asm volatile("cp.async.cg.shared.global [%0], [%1], 16;" :: "r"(dst), "l"(src))
#define CP_COMMIT() asm volatile("cp.async.commit_group;")
#define CP_WAIT0()  asm volatile("cp.async.wait_group 0;")
#define LDSM_X4(r0, r1, r2, r3, addr) \
    asm volatile("ldmatrix.sync.aligned.m8n8.x4.shared.b16 {%0,%1,%2,%3}, [%4];" \
        : "=r"(r0), "=r"(r1), "=r"(r2), "=r"(r3) : "r"(addr))
#define MMA16816(d, a, b0, b1) \
    asm volatile("mma.sync.aligned.m16n8k16.row.col.f32.bf16.bf16.f32 " \
        "{%0,%1,%2,%3}, {%4,%5,%6,%7}, {%8,%9}, {%0,%1,%2,%3};" \
        : "+f"((d)[0]), "+f"((d)[1]), "+f"((d)[2]), "+f"((d)[3]) \
        : "r"((a)[0]), "r"((a)[1]), "r"((a)[2]), "r"((a)[3]), "r"(b0), "r"(b1))

// ---------------- hi/lo split helpers ----------------
__device__ __forceinline__ void split_hilo(float x, __nv_bfloat16& h, __nv_bfloat16& l) {
    h = __float2bfloat16(x);
    l = __float2bfloat16(x - __bfloat162float(h));
}

// ---------------- fused LayerNorm + hi/lo emit: one block per row of 1024 ----------------
__global__ __launch_bounds__(256) void ln_hilo_kernel(const float* __restrict__ X,
                                                      const float* __restrict__ gma,
                                                      const float* __restrict__ bta,
                                                      __nv_bfloat16* __restrict__ Ho,
                                                      __nv_bfloat16* __restrict__ Lo) {
    int row = blockIdx.x;
    int tid = threadIdx.x;
    const float4* xr = (const float4*)(X + (size_t)row * DMODEL);
    float4 x4 = xr[tid];
    float s  = x4.x + x4.y + x4.z + x4.w;
    float ss = x4.x*x4.x + x4.y*x4.y + x4.z*x4.z + x4.w*x4.w;
#pragma unroll
    for (int off = 16; off > 0; off >>= 1) {
        s  += __shfl_xor_sync(0xffffffffu, s,  off);
        ss += __shfl_xor_sync(0xffffffffu, ss, off);
    }
    __shared__ float red[16];
    int lane = tid & 31, wid = tid >> 5;
    if (lane == 0) { red[wid] = s; red[8 + wid] = ss; }
    __syncthreads();
    float tot = 0.f, tot2 = 0.f;
#pragma unroll
    for (int i = 0; i < 8; i++) { tot += red[i]; tot2 += red[8 + i]; }
    const float inv = 1.0f / (float)DMODEL;
    float mu  = tot * inv;
    float var = tot2 * inv - mu * mu;
    float rs  = rsqrtf(var + 1e-5f);
    float4 gv = ((const float4*)gma)[tid];
    float4 bv = ((const float4*)bta)[tid];
    float o0 = (x4.x - mu) * rs * gv.x + bv.x;
    float o1 = (x4.y - mu) * rs * gv.y + bv.y;
    float o2 = (x4.z - mu) * rs * gv.z + bv.z;
    float o3 = (x4.w - mu) * rs * gv.w + bv.w;
    union { __nv_bfloat16 b[4]; uint2 u; } ph, pl;
    split_hilo(o0, ph.b[0], pl.b[0]);
    split_hilo(o1, ph.b[1], pl.b[1]);
    split_hilo(o2, ph.b[2], pl.b[2]);
    split_hilo(o3, ph.b[3], pl.b[3]);
    size_t base = (size_t)row * DMODEL + tid * 4;
    *(uint2*)(Ho + base) = ph.u;
    *(uint2*)(Lo + base) = pl.u;
}

// ---------------- elementwise fp32 -> bf16 hi/lo ----------------
__global__ __launch_bounds__(256) void hilo_kernel(const float* __restrict__ X,
                                                   __nv_bfloat16* __restrict__ Ho,
                                                   __nv_bfloat16* __restrict__ Lo) {
    size_t idx = (size_t)blockIdx.x * 256 + threadIdx.x;
    float4 v = ((const float4*)X)[idx];
    union { __nv_bfloat16 b[4]; uint2 u; } ph, pl;
    split_hilo(v.x, ph.b[0], pl.b[0]);
    split_hilo(v.y, ph.b[1], pl.b[1]);
    split_hilo(v.z, ph.b[2], pl.b[2]);
    split_hilo(v.w, ph.b[3], pl.b[3]);
    *(uint2*)(Ho + idx * 4) = ph.u;
    *(uint2*)(Lo + idx * 4) = pl.u;
}

// ---------------- weight convert + transpose: W[K,N] fp32 -> Ht/Lt[N,K] bf16 ----------------
__global__ __launch_bounds__(256) void tconv_kernel(const float* __restrict__ W,
                                                    __nv_bfloat16* __restrict__ Ht,
                                                    __nv_bfloat16* __restrict__ Lt,
                                                    int K, int N) {
    __shared__ float s[32][33];
    int tx = threadIdx.x, ty = threadIdx.y;
    int n0 = blockIdx.x * 32, k0 = blockIdx.y * 32;
#pragma unroll
    for (int i = 0; i < 4; i++)
        s[ty + 8 * i][tx] = W[(size_t)(k0 + ty + 8 * i) * N + n0 + tx];
    __syncthreads();
#pragma unroll
    for (int i = 0; i < 4; i++) {
        int n = ty + 8 * i, k = tx;
        float v = s[k][n];
        __nv_bfloat16 h, l;
        split_hilo(v, h, l);
        size_t off = (size_t)(n0 + n) * K + k0 + k;
        Ht[off] = h;
        Lt[off] = l;
    }
}

// ---------------- bf16x3 GEMM via mma.sync (HMMA tensor path) ----------------
// C[M,N] = A[M,K] @ Bt[N,K]^T, 3-term split: AhBh + AhBl + AlBh.
// BM=BN=128, BK=32, 256 threads = 8 warps (2M x 4N), warp tile 64x32.
// Smem swizzle: 64B rows (32 bf16), 16B chunk c stored at c ^ ((row>>1)&3).
__global__ __launch_bounds__(256) void gemm_mma_kernel(const __nv_bfloat16* __restrict__ Ah,
                                                       const __nv_bfloat16* __restrict__ Al,
                                                       const __nv_bfloat16* __restrict__ Bh,
                                                       const __nv_bfloat16* __restrict__ Bl,
                                                       float* __restrict__ C,
                                                       int M, int N, int K,
                                                       const float* __restrict__ bias,
                                                       const float* __restrict__ resid) {
    __shared__ __nv_bfloat16 As[2][128 * 32];
    __shared__ __nv_bfloat16 Bs[2][128 * 32];
    int tid = threadIdx.x;
    int warp = tid >> 5, lane = tid & 31;
    int wm = (warp & 1) * 64, wn = (warp >> 1) * 32;
    int row0 = blockIdx.y * 128, col0 = blockIdx.x * 128;
    uint32_t as_base = smem_to_u32(As);
    uint32_t bs_base = smem_to_u32(Bs);

    const __nv_bfloat16* Aterm[3] = { Ah, Ah, Al };
    const __nv_bfloat16* Bterm[3] = { Bh, Bl, Bh };
    const int nk = K / 32;
    const int total = 3 * nk;

    float acc[4][4][4];
#pragma unroll
    for (int mi = 0; mi < 4; mi++)
#pragma unroll
        for (int ni = 0; ni < 4; ni++)
#pragma unroll
            for (int e = 0; e < 4; e++) acc[mi][ni][e] = 0.f;

    // tile loader: 512 16B-chunks per matrix, 2 per thread
    auto load_tiles = [&](int buf, const __nv_bfloat16* Ap, const __nv_bfloat16* Bp, int k0) {
#pragma unroll
        for (int i = 0; i < 2; i++) {
            int lci = tid + i * 256;
            int r = lci >> 2, c = lci & 3;
            int pc = c ^ ((r >> 1) & 3);
            uint32_t doff = (uint32_t)(buf * 8192 + r * 64 + pc * 16);
            CP_ASYNC16(as_base + doff, Ap + (size_t)(row0 + r) * K + k0 + c * 8);
            CP_ASYNC16(bs_base + doff, Bp + (size_t)(col0 + r) * K + k0 + c * 8);
        }
    };

    load_tiles(0, Aterm[0], Bterm[0], 0);
    CP_COMMIT();

    for (int it = 0; it < total; it++) {
        int buf = it & 1;
        CP_WAIT0();
        __syncthreads();
        if (it + 1 < total) {
            int t  = (it + 1) / nk;
            int kc = ((it + 1) % nk) * 32;
            load_tiles(buf ^ 1, Aterm[t], Bterm[t], kc);
            CP_COMMIT();
        }
        uint32_t abase = as_base + buf * 8192;
        uint32_t bbase = bs_base + buf * 8192;
#pragma unroll
        for (int kk = 0; kk < 2; kk++) {
            uint32_t afr[4][4];
#pragma unroll
            for (int mi = 0; mi < 4; mi++) {
                int r = wm + mi * 16 + (lane & 15);
                int c = kk * 2 + (lane >> 4);
                uint32_t addr = abase + r * 64 + (uint32_t)((c ^ ((r >> 1) & 3)) * 16);
                LDSM_X4(afr[mi][0], afr[mi][1], afr[mi][2], afr[mi][3], addr);
            }
            uint32_t bfr[2][4];
#pragma unroll
            for (int nb = 0; nb < 2; nb++) {
                int r = wn + nb * 16 + (lane & 15);
                int c = kk * 2 + (lane >> 4);
                uint32_t addr = bbase + r * 64 + (uint32_t)((c ^ ((r >> 1) & 3)) * 16);
                LDSM_X4(bfr[nb][0], bfr[nb][1], bfr[nb][2], bfr[nb][3], addr);
            }
#pragma unroll
            for (int mi = 0; mi < 4; mi++)
#pragma unroll
                for (int nb = 0; nb < 2; nb++) {
                    MMA16816(acc[mi][nb * 2 + 0], afr[mi], bfr[nb][0], bfr[nb][2]);
                    MMA16816(acc[mi][nb * 2 + 1], afr[mi], bfr[nb][1], bfr[nb][3]);
                }
        }
        __syncthreads();
    }

    // epilogue: fragment -> global, fused bias + residual
    int grow = row0 + wm;
    int gcol = col0 + wn;
#pragma unroll
    for (int mi = 0; mi < 4; mi++)
#pragma unroll
        for (int ni = 0; ni < 4; ni++) {
            int r  = grow + mi * 16 + (lane >> 2);
            int cc = gcol + ni * 8 + (lane & 3) * 2;
            float2 v0 = make_float2(acc[mi][ni][0], acc[mi][ni][1]);
            float2 v1 = make_float2(acc[mi][ni][2], acc[mi][ni][3]);
            if (bias) {
                float2 b2 = *(const float2*)(bias + cc);
                v0.x += b2.x; v0.y += b2.y;
                v1.x += b2.x; v1.y += b2.y;
            }
            if (resid) {
                float2 r0 = *(const float2*)(resid + (size_t)r * N + cc);
                float2 r1 = *(const float2*)(resid + (size_t)(r + 8) * N + cc);
                v0.x += r0.x; v0.y += r0.y;
                v1.x += r1.x; v1.y += r1.y;
            }
            *(float2*)(C + (size_t)r * N + cc) = v0;
            *(float2*)(C + (size_t)(r + 8) * N + cc) = v1;
        }
}

// ---------------- fp32 GEMM (kept for small ctx projections) ----------------
__global__ __launch_bounds__(256) void gemm_kernel(const float* __restrict__ A,
                                                   const float* __restrict__ B,
                                                   float* __restrict__ C,
                                                   int M, int N, int K,
                                                   const float* __restrict__ bias,
                                                   const float* __restrict__ resid) {
    __shared__ float As[16][128];
    __shared__ float Bs[16][128];
    int tid = threadIdx.x;
    int tx = tid & 15, ty = tid >> 4;
    int row0 = blockIdx.y * 128, col0 = blockIdx.x * 128;
    float acc[8][8];
#pragma unroll
    for (int i = 0; i < 8; i++)
#pragma unroll
        for (int j = 0; j < 8; j++) acc[i][j] = 0.f;

    for (int k0 = 0; k0 < K; k0 += 16) {
#pragma unroll
        for (int i = 0; i < 2; i++) {
            int idx = tid * 2 + i;
            int r = idx >> 2, kc = idx & 3;
            int gr = row0 + r;
            float4 f = make_float4(0.f, 0.f, 0.f, 0.f);
            if (gr < M) f = *(const float4*)(A + (size_t)gr * K + k0 + kc * 4);
            As[kc * 4 + 0][r] = f.x;
            As[kc * 4 + 1][r] = f.y;
            As[kc * 4 + 2][r] = f.z;
            As[kc * 4 + 3][r] = f.w;
        }
#pragma unroll
        for (int i = 0; i < 2; i++) {
            int idx = tid * 2 + i;
            int kb = idx >> 5, nc = idx & 31;
            float4 f = *(const float4*)(B + (size_t)(k0 + kb) * N + col0 + nc * 4);
            *(float4*)&Bs[kb][nc * 4] = f;
        }
        __syncthreads();
#pragma unroll
        for (int kk = 0; kk < 16; kk++) {
            float a[8], bb[8];
            *(float4*)&a[0]  = *(float4*)&As[kk][ty * 8];
            *(float4*)&a[4]  = *(float4*)&As[kk][ty * 8 + 4];
            *(float4*)&bb[0] = *(float4*)&Bs[kk][tx * 4];
            *(float4*)&bb[4] = *(float4*)&Bs[kk][64 + tx * 4];
#pragma unroll
            for (int i = 0; i < 8; i++)
#pragma unroll
                for (int j = 0; j < 8; j++) acc[i][j] += a[i] * bb[j];
        }
        __syncthreads();
    }
#pragma unroll
    for (int i = 0; i < 8; i++) {
        int gr = row0 + ty * 8 + i;
        if (gr >= M) continue;
#pragma unroll
        for (int half = 0; half < 2; half++) {
            int gc = col0 + half * 64 + tx * 4;
            float4 r4;
            r4.x = acc[i][half * 4 + 0];
            r4.y = acc[i][half * 4 + 1];
            r4.z = acc[i][half * 4 + 2];
            r4.w = acc[i][half * 4 + 3];
            if (bias) {
                float4 b4 = *(const float4*)(bias + gc);
                r4.x += b4.x; r4.y += b4.y; r4.z += b4.z; r4.w += b4.w;
            }
            if (resid) {
                float4 q4 = *(const float4*)(resid + (size_t)gr * N + gc);
                r4.x += q4.x; r4.y += q4.y; r4.z += q4.z; r4.w += q4.w;
            }
            *(float4*)(C + (size_t)gr * N + gc) = r4;
        }
    }
}

// ---------------- flash attention (fp32) ----------------
#define ATTN_SMEM_FLOATS (4096 + 64 * 68 + 4096 + 4096)
__global__ __launch_bounds__(256) void attn_kernel(const float* __restrict__ Q,
                                                   const float* __restrict__ Kp,
                                                   const float* __restrict__ V,
                                                   float* __restrict__ O,
                                                   int qlen, int kvlen) {
    extern __shared__ float sm[];
    float (*qs)[64] = (float(*)[64])sm;
    float (*ks)[68] = (float(*)[68])(sm + 4096);
    float (*vs)[64] = (float(*)[64])(sm + 4096 + 64 * 68);
    float (*ps)[64] = (float(*)[64])(sm + 4096 + 64 * 68 + 4096);

    int b = blockIdx.z, h = blockIdx.y, qt = blockIdx.x;
    int tid = threadIdx.x;
    int tx = tid & 15, ty = tid >> 4;

    const size_t qoff = ((size_t)(b * qlen) + qt * 64) * DMODEL + h * DHEAD;
#pragma unroll
    for (int i = 0; i < 4; i++) {
        int idx = tid + i * 256;
        int r = idx >> 4, c = (idx & 15) * 4;
        *(float4*)&qs[r][c] = *(const float4*)(Q + qoff + (size_t)r * DMODEL + c);
    }

    float m_[4], l_[4], oacc[4][4];
#pragma unroll
    for (int i = 0; i < 4; i++) {
        m_[i] = -1e30f; l_[i] = 0.f;
#pragma unroll
        for (int j = 0; j < 4; j++) oacc[i][j] = 0.f;
    }

    int ntiles = (kvlen + 63) >> 6;
    for (int kt = 0; kt < ntiles; kt++) {
#pragma unroll
        for (int i = 0; i < 4; i++) {
            int idx = tid + i * 256;
            int r = idx >> 4, c = (idx & 15) * 4;
            int kr = kt * 64 + r;
            float4 kf = make_float4(0.f, 0.f, 0.f, 0.f), vf = kf;
            if (kr < kvlen) {
                size_t off = ((size_t)(b * kvlen + kr)) * DMODEL + h * DHEAD + c;
                kf = *(const float4*)(Kp + off);
                vf = *(const float4*)(V + off);
            }
            *(float4*)&ks[r][c] = kf;
            *(float4*)&vs[r][c] = vf;
        }
        __syncthreads();

        float s[4][4];
#pragma unroll
        for (int i = 0; i < 4; i++)
#pragma unroll
            for (int j = 0; j < 4; j++) s[i][j] = 0.f;

#pragma unroll
        for (int dd = 0; dd < 64; dd += 4) {
            float4 qa[4], kb4[4];
#pragma unroll
            for (int i = 0; i < 4; i++) qa[i]  = *(float4*)&qs[ty * 4 + i][dd];
#pragma unroll
            for (int j = 0; j < 4; j++) kb4[j] = *(float4*)&ks[tx * 4 + j][dd];
#pragma unroll
            for (int i = 0; i < 4; i++)
#pragma unroll
                for (int j = 0; j < 4; j++)
                    s[i][j] += qa[i].x * kb4[j].x + qa[i].y * kb4[j].y +
                               qa[i].z * kb4[j].z + qa[i].w * kb4[j].w;
        }
#pragma unroll
        for (int i = 0; i < 4; i++)
#pragma unroll
            for (int j = 0; j < 4; j++) {
                int kc = kt * 64 + tx * 4 + j;
                s[i][j] = (kc < kvlen) ? s[i][j] * 0.125f : -1e30f;
            }
#pragma unroll
        for (int i = 0; i < 4; i++) {
            float mloc = fmaxf(fmaxf(s[i][0], s[i][1]), fmaxf(s[i][2], s[i][3]));
#pragma unroll
            for (int off = 1; off < 16; off <<= 1)
                mloc = fmaxf(mloc, __shfl_xor_sync(0xffffffffu, mloc, off));
            float mnew  = fmaxf(m_[i], mloc);
            float alpha = __expf(m_[i] - mnew);
            float p0 = __expf(s[i][0] - mnew);
            float p1 = __expf(s[i][1] - mnew);
            float p2 = __expf(s[i][2] - mnew);
            float p3 = __expf(s[i][3] - mnew);
            float psum = p0 + p1 + p2 + p3;
#pragma unroll
            for (int off = 1; off < 16; off <<= 1)
                psum += __shfl_xor_sync(0xffffffffu, psum, off);
            l_[i] = l_[i] * alpha + psum;
            m_[i] = mnew;
#pragma unroll
            for (int j = 0; j < 4; j++) oacc[i][j] *= alpha;
            float4 pv = make_float4(p0, p1, p2, p3);
            *(float4*)&ps[ty * 4 + i][tx * 4] = pv;
        }
        __syncthreads();
#pragma unroll
        for (int kk = 0; kk < 64; kk += 4) {
            float4 vr0 = *(float4*)&vs[kk + 0][tx * 4];
            float4 vr1 = *(float4*)&vs[kk + 1][tx * 4];
            float4 vr2 = *(float4*)&vs[kk + 2][tx * 4];
            float4 vr3 = *(float4*)&vs[kk + 3][tx * 4];
#pragma unroll
            for (int i = 0; i < 4; i++) {
                float4 pa = *(float4*)&ps[ty * 4 + i][kk];
                oacc[i][0] += pa.x * vr0.x + pa.y * vr1.x + pa.z * vr2.x + pa.w * vr3.x;
                oacc[i][1] += pa.x * vr0.y + pa.y * vr1.y + pa.z * vr2.y + pa.w * vr3.y;
                oacc[i][2] += pa.x * vr0.z + pa.y * vr1.z + pa.z * vr2.z + pa.w * vr3.z;
                oacc[i][3] += pa.x * vr0.w + pa.y * vr1.w + pa.z * vr2.w + pa.w * vr3.w;
            }
        }
        __syncthreads();
    }
#pragma unroll
    for (int i = 0; i < 4; i++) {
        float inv = 1.0f / l_[i];
        float4 o4 = make_float4(oacc[i][0] * inv, oacc[i][1] * inv,
                                oacc[i][2] * inv, oacc[i][3] * inv);
        int r = ty * 4 + i;
        *(float4*)(O + qoff + (size_t)r * DMODEL + tx * 4) = o4;
    }
}

// ---------------- GeGLU + hi/lo emit ----------------
__global__ __launch_bounds__(256) void geglu_hilo_kernel(const float* __restrict__ Hb,
                                                         __nv_bfloat16* __restrict__ Ho,
                                                         __nv_bfloat16* __restrict__ Lo) {
    int row = blockIdx.y;
    int c = (blockIdx.x * 256 + threadIdx.x) * 4;
    const float* hr = Hb + (size_t)row * FFH;
    float4 u = *(const float4*)(hr + c);
    float4 g = *(const float4*)(hr + FFHALF + c);
    const float k = 0.70710678118654752f;
    float r0 = u.x * (0.5f * g.x * (1.f + erff(g.x * k)));
    float r1 = u.y * (0.5f * g.y * (1.f + erff(g.y * k)));
    float r2 = u.z * (0.5f * g.z * (1.f + erff(g.z * k)));
    float r3 = u.w * (0.5f * g.w * (1.f + erff(g.w * k)));
    union { __nv_bfloat16 b[4]; uint2 uu; } ph, pl;
    split_hilo(r0, ph.b[0], pl.b[0]);
    split_hilo(r1, ph.b[1], pl.b[1]);
    split_hilo(r2, ph.b[2], pl.b[2]);
    split_hilo(r3, ph.b[3], pl.b[3]);
    size_t base = (size_t)row * FFHALF + c;
    *(uint2*)(Ho + base) = ph.uu;
    *(uint2*)(Lo + base) = pl.uu;
}

// ---------------- launch ----------------
extern "C" void kernel_launch(void* const* d_in, const int* in_sizes, int n_in,
                              void* d_out, int out_size) {
    const float* x    = (const float*)d_in[0];
    const float* ctx  = (const float*)d_in[1];
    const float* ln1g = (const float*)d_in[2];
    const float* ln1b = (const float*)d_in[3];
    const float* ln2g = (const float*)d_in[4];
    const float* ln2b = (const float*)d_in[5];
    const float* ln3g = (const float*)d_in[6];
    const float* ln3b = (const float*)d_in[7];
    const float* a1wq = (const float*)d_in[8];
    const float* a1wk = (const float*)d_in[9];
    const float* a1wv = (const float*)d_in[10];
    const float* a1wo = (const float*)d_in[11];
    const float* a1bo = (const float*)d_in[12];
    const float* a2wq = (const float*)d_in[13];
    const float* a2wk = (const float*)d_in[14];
    const float* a2wv = (const float*)d_in[15];
    const float* a2wo = (const float*)d_in[16];
    const float* a2bo = (const float*)d_in[17];
    const float* ffw1 = (const float*)d_in[18];
    const float* ffb1 = (const float*)d_in[19];
    const float* ffw2 = (const float*)d_in[20];
    const float* ffb2 = (const float*)d_in[21];
    float* out = (float*)d_out;

    float *q, *k, *v, *o, *xa, *h;
    __nv_bfloat16 *ah, *al, *bh, *bl;
    cudaGetSymbolAddress((void**)&q,  g_q);
    cudaGetSymbolAddress((void**)&k,  g_k);
    cudaGetSymbolAddress((void**)&v,  g_v);
    cudaGetSymbolAddress((void**)&o,  g_o);
    cudaGetSymbolAddress((void**)&xa, g_xa);
    cudaGetSymbolAddress((void**)&h,  g_h);
    cudaGetSymbolAddress((void**)&ah, g_ah);
    cudaGetSymbolAddress((void**)&al, g_al);
    cudaGetSymbolAddress((void**)&bh, g_bh);
    cudaGetSymbolAddress((void**)&bl, g_bl);

    const int attn_smem = ATTN_SMEM_FLOATS * 4;
    cudaFuncSetAttribute(attn_kernel, cudaFuncAttributeMaxDynamicSharedMemorySize, attn_smem);

    dim3 blk(256);
    dim3 tblk(32, 8);
    dim3 tc1024(DMODEL / 128, MROWS / 128);         // (8, 64)
    dim3 tcFF1(FFH / 128, MROWS / 128);             // (64, 64)
    dim3 gemmCtx(DMODEL / 128, (CTXROWS + 127) / 128);
    dim3 attng(SEQ / 64, NHEAD, 4);
    dim3 tg1024(DMODEL / 32, DMODEL / 32);
    dim3 tgFF1(FFH / 32, DMODEL / 32);
    dim3 tgFF2(DMODEL / 32, FFHALF / 32);
    int hiloBlocks1024 = (MROWS * DMODEL) / 1024;

    // --- self attention ---
    ln_hilo_kernel<<<MROWS, blk>>>(x, ln1g, ln1b, ah, al);
    tconv_kernel<<<tg1024, tblk>>>(a1wq, bh, bl, DMODEL, DMODEL);
    gemm_mma_kernel<<<tc1024, blk>>>(ah, al, bh, bl, q, MROWS, DMODEL, DMODEL, nullptr, nullptr);
    tconv_kernel<<<tg1024, tblk>>>(a1wk, bh, bl, DMODEL, DMODEL);
    gemm_mma_kernel<<<tc1024, blk>>>(ah, al, bh, bl, k, MROWS, DMODEL, DMODEL, nullptr, nullptr);
    tconv_kernel<<<tg1024, tblk>>>(a1wv, bh, bl, DMODEL, DMODEL);
    gemm_mma_kernel<<<tc1024, blk>>>(ah, al, bh, bl, v, MROWS, DMODEL, DMODEL, nullptr, nullptr);
    attn_kernel<<<attng, blk, attn_smem>>>(q, k, v, o, SEQ, SEQ);
    hilo_kernel<<<hiloBlocks1024, blk>>>(o, ah, al);
    tconv_kernel<<<tg1024, tblk>>>(a1wo, bh, bl, DMODEL, DMODEL);
    gemm_mma_kernel<<<tc1024, blk>>>(ah, al, bh, bl, xa, MROWS, DMODEL, DMODEL, a1bo, x);

    // --- cross attention ---
    ln_hilo_kernel<<<MROWS, blk>>>(xa, ln2g, ln2b, ah, al);
    tconv_kernel<<<tg1024, tblk>>>(a2wq, bh, bl, DMODEL, DMODEL);
    gemm_mma_kernel<<<tc1024, blk>>>(ah, al, bh, bl, q, MROWS, DMODEL, DMODEL, nullptr, nullptr);
    gemm_kernel<<<gemmCtx, blk>>>(ctx, a2wk, k, CTXROWS, DMODEL, CTXDIM, nullptr, nullptr);
    gemm_kernel<<<gemmCtx, blk>>>(ctx, a2wv, v, CTXROWS, DMODEL, CTXDIM, nullptr, nullptr);
    attn_kernel<<<attng, blk, attn_smem>>>(q, k, v, o, SEQ, CTXLEN);
    hilo_kernel<<<hiloBlocks1024, blk>>>(o, ah, al);
    tconv_kernel<<<tg1024, tblk>>>(a2wo, bh, bl, DMODEL, DMODEL);
    gemm_mma_kernel<<<tc1024, blk>>>(ah, al, bh, bl, xa, MROWS, DMODEL, DMODEL, a2bo, xa);

    // --- GeGLU feed-forward ---
    ln_hilo_kernel<<<MROWS, blk>>>(xa, ln3g, ln3b, ah, al);
    tconv_kernel<<<tgFF1, tblk>>>(ffw1, bh, bl, DMODEL, FFH);
    gemm_mma_kernel<<<tcFF1, blk>>>(ah, al, bh, bl, h, MROWS, FFH, DMODEL, ffb1, nullptr);
    geglu_hilo_kernel<<<dim3(FFHALF / 1024, MROWS), blk>>>(h, ah, al);
    tconv_kernel<<<tgFF2, tblk>>>(ffw2, bh, bl, FFHALF, DMODEL);
    gemm_mma_kernel<<<tc1024, blk>>>(ah, al, bh, bl, out, MROWS, DMODEL, FFHALF, ffb2, xa);
}

// round 5
// speedup vs baseline: 2.3824x; 1.4267x over previous
#include <cuda_runtime.h>
#include <cuda_bf16.h>
#include <math.h>
#include <cstdint>

// ---------------- problem constants ----------------
#define MROWS   8192        // B*S
#define DMODEL  1024
#define NHEAD   16
#define DHEAD   64
#define SEQ     2048
#define CTXROWS 308         // B*77
#define CTXLEN  77
#define CTXDIM  768
#define FFH     8192
#define FFHALF  4096

// ---------------- scratch (static device globals; no runtime alloc) ----------------
__device__ float g_xa[MROWS * DMODEL];
__device__ float g_h [(size_t)MROWS * FFH];
__device__ float g_ctmp1[CTXROWS * DMODEL];
__device__ float g_ctmp2[CTXROWS * DMODEL];
__device__ __nv_bfloat16 g_ah[(size_t)MROWS * FFHALF];   // activation hi
__device__ __nv_bfloat16 g_al[(size_t)MROWS * FFHALF];   // activation lo
__device__ __nv_bfloat16 g_bh[(size_t)FFH * DMODEL];     // weight hi (transposed [N,K])
__device__ __nv_bfloat16 g_bl[(size_t)FFH * DMODEL];     // weight lo
__device__ __nv_bfloat16 g_qh[MROWS * DMODEL];
__device__ __nv_bfloat16 g_ql[MROWS * DMODEL];
__device__ __nv_bfloat16 g_kh[MROWS * DMODEL];
__device__ __nv_bfloat16 g_kl[MROWS * DMODEL];
__device__ __nv_bfloat16 g_vh[MROWS * DMODEL];
__device__ __nv_bfloat16 g_vl[MROWS * DMODEL];
__device__ __nv_bfloat16 g_oh[MROWS * DMODEL];
__device__ __nv_bfloat16 g_ol[MROWS * DMODEL];

// ---------------- PTX helpers ----------------
__device__ __forceinline__ uint32_t smem_to_u32(const void* p) {
    uint32_t a;
    asm("{ .reg .u64 t; cvta.to.shared.u64 t, %1; cvt.u32.u64 %0, t; }" : "=r"(a) : "l"(p));
    return a;
}
#define CP_ASYNC16(dst, src) \
    asm volatile("cp.async.cg.shared.global [%0], [%1], 16;" :: "r"(dst), "l"(src))
#define CP_COMMIT() asm volatile("cp.async.commit_group;")
#define CP_WAIT0()  asm volatile("cp.async.wait_group 0;")
#define LDSM_X4(r0, r1, r2, r3, addr) \
    asm volatile("ldmatrix.sync.aligned.m8n8.x4.shared.b16 {%0,%1,%2,%3}, [%4];" \
        : "=r"(r0), "=r"(r1), "=r"(r2), "=r"(r3) : "r"(addr))
#define MMA16816(d, a, b0, b1) \
    asm volatile("mma.sync.aligned.m16n8k16.row.col.f32.bf16.bf16.f32 " \
        "{%0,%1,%2,%3}, {%4,%5,%6,%7}, {%8,%9}, {%0,%1,%2,%3};" \
        : "+f"((d)[0]), "+f"((d)[1]), "+f"((d)[2]), "+f"((d)[3]) \
        : "r"((a)[0]), "r"((a)[1]), "r"((a)[2]), "r"((a)[3]), "r"(b0), "r"(b1))

// ---------------- hi/lo split helpers ----------------
__device__ __forceinline__ void split_hilo(float x, __nv_bfloat16& h, __nv_bfloat16& l) {
    h = __float2bfloat16(x);
    l = __float2bfloat16(x - __bfloat162float(h));
}
__device__ __forceinline__ uint32_t pack_bf2(__nv_bfloat16 lo, __nv_bfloat16 hi) {
    __nv_bfloat162 t; t.x = lo; t.y = hi;
    return *(uint32_t*)&t;
}

// ---------------- fused LayerNorm + hi/lo emit ----------------
__global__ __launch_bounds__(256) void ln_hilo_kernel(const float* __restrict__ X,
                                                      const float* __restrict__ gma,
                                                      const float* __restrict__ bta,
                                                      __nv_bfloat16* __restrict__ Ho,
                                                      __nv_bfloat16* __restrict__ Lo) {
    int row = blockIdx.x;
    int tid = threadIdx.x;
    const float4* xr = (const float4*)(X + (size_t)row * DMODEL);
    float4 x4 = xr[tid];
    float s  = x4.x + x4.y + x4.z + x4.w;
    float ss = x4.x*x4.x + x4.y*x4.y + x4.z*x4.z + x4.w*x4.w;
#pragma unroll
    for (int off = 16; off > 0; off >>= 1) {
        s  += __shfl_xor_sync(0xffffffffu, s,  off);
        ss += __shfl_xor_sync(0xffffffffu, ss, off);
    }
    __shared__ float red[16];
    int lane = tid & 31, wid = tid >> 5;
    if (lane == 0) { red[wid] = s; red[8 + wid] = ss; }
    __syncthreads();
    float tot = 0.f, tot2 = 0.f;
#pragma unroll
    for (int i = 0; i < 8; i++) { tot += red[i]; tot2 += red[8 + i]; }
    const float inv = 1.0f / (float)DMODEL;
    float mu  = tot * inv;
    float var = tot2 * inv - mu * mu;
    float rs  = rsqrtf(var + 1e-5f);
    float4 gv = ((const float4*)gma)[tid];
    float4 bv = ((const float4*)bta)[tid];
    float o0 = (x4.x - mu) * rs * gv.x + bv.x;
    float o1 = (x4.y - mu) * rs * gv.y + bv.y;
    float o2 = (x4.z - mu) * rs * gv.z + bv.z;
    float o3 = (x4.w - mu) * rs * gv.w + bv.w;
    union { __nv_bfloat16 b[4]; uint2 u; } ph, pl;
    split_hilo(o0, ph.b[0], pl.b[0]);
    split_hilo(o1, ph.b[1], pl.b[1]);
    split_hilo(o2, ph.b[2], pl.b[2]);
    split_hilo(o3, ph.b[3], pl.b[3]);
    size_t base = (size_t)row * DMODEL + tid * 4;
    *(uint2*)(Ho + base) = ph.u;
    *(uint2*)(Lo + base) = pl.u;
}

// ---------------- elementwise fp32 -> bf16 hi/lo (ctx K/V path) ----------------
__global__ __launch_bounds__(256) void hilo_kernel(const float* __restrict__ X,
                                                   __nv_bfloat16* __restrict__ Ho,
                                                   __nv_bfloat16* __restrict__ Lo) {
    size_t idx = (size_t)blockIdx.x * 256 + threadIdx.x;
    float4 v = ((const float4*)X)[idx];
    union { __nv_bfloat16 b[4]; uint2 u; } ph, pl;
    split_hilo(v.x, ph.b[0], pl.b[0]);
    split_hilo(v.y, ph.b[1], pl.b[1]);
    split_hilo(v.z, ph.b[2], pl.b[2]);
    split_hilo(v.w, ph.b[3], pl.b[3]);
    *(uint2*)(Ho + idx * 4) = ph.u;
    *(uint2*)(Lo + idx * 4) = pl.u;
}

// ---------------- weight convert + transpose: W[K,N] fp32 -> Ht/Lt[N,K] bf16 ----------------
__global__ __launch_bounds__(256) void tconv_kernel(const float* __restrict__ W,
                                                    __nv_bfloat16* __restrict__ Ht,
                                                    __nv_bfloat16* __restrict__ Lt,
                                                    int K, int N) {
    __shared__ float s[32][33];
    int tx = threadIdx.x, ty = threadIdx.y;
    int n0 = blockIdx.x * 32, k0 = blockIdx.y * 32;
#pragma unroll
    for (int i = 0; i < 4; i++)
        s[ty + 8 * i][tx] = W[(size_t)(k0 + ty + 8 * i) * N + n0 + tx];
    __syncthreads();
#pragma unroll
    for (int i = 0; i < 4; i++) {
        int n = ty + 8 * i, k = tx;
        float v = s[k][n];
        __nv_bfloat16 h, l;
        split_hilo(v, h, l);
        size_t off = (size_t)(n0 + n) * K + k0 + k;
        Ht[off] = h;
        Lt[off] = l;
    }
}

// ---------------- bf16x3 GEMM via mma.sync ----------------
// C[M,N] = A @ Bt^T (3-term split). Optional hi/lo bf16 output (CH/CL) or fp32 C.
__global__ __launch_bounds__(256) void gemm_mma_kernel(const __nv_bfloat16* __restrict__ Ah,
                                                       const __nv_bfloat16* __restrict__ Al,
                                                       const __nv_bfloat16* __restrict__ Bh,
                                                       const __nv_bfloat16* __restrict__ Bl,
                                                       float* __restrict__ C,
                                                       int M, int N, int K,
                                                       const float* __restrict__ bias,
                                                       const float* __restrict__ resid,
                                                       __nv_bfloat16* __restrict__ CH,
                                                       __nv_bfloat16* __restrict__ CL) {
    __shared__ __nv_bfloat16 As[2][128 * 32];
    __shared__ __nv_bfloat16 Bs[2][128 * 32];
    int tid = threadIdx.x;
    int warp = tid >> 5, lane = tid & 31;
    int wm = (warp & 1) * 64, wn = (warp >> 1) * 32;
    int row0 = blockIdx.y * 128, col0 = blockIdx.x * 128;
    uint32_t as_base = smem_to_u32(As);
    uint32_t bs_base = smem_to_u32(Bs);

    const __nv_bfloat16* Aterm[3] = { Ah, Ah, Al };
    const __nv_bfloat16* Bterm[3] = { Bh, Bl, Bh };
    const int nk = K / 32;
    const int total = 3 * nk;

    float acc[4][4][4];
#pragma unroll
    for (int mi = 0; mi < 4; mi++)
#pragma unroll
        for (int ni = 0; ni < 4; ni++)
#pragma unroll
            for (int e = 0; e < 4; e++) acc[mi][ni][e] = 0.f;

    auto load_tiles = [&](int buf, const __nv_bfloat16* Ap, const __nv_bfloat16* Bp, int k0) {
#pragma unroll
        for (int i = 0; i < 2; i++) {
            int lci = tid + i * 256;
            int r = lci >> 2, c = lci & 3;
            int pc = c ^ ((r >> 1) & 3);
            uint32_t doff = (uint32_t)(buf * 8192 + r * 64 + pc * 16);
            CP_ASYNC16(as_base + doff, Ap + (size_t)(row0 + r) * K + k0 + c * 8);
            CP_ASYNC16(bs_base + doff, Bp + (size_t)(col0 + r) * K + k0 + c * 8);
        }
    };

    load_tiles(0, Aterm[0], Bterm[0], 0);
    CP_COMMIT();

    for (int it = 0; it < total; it++) {
        int buf = it & 1;
        CP_WAIT0();
        __syncthreads();
        if (it + 1 < total) {
            int t  = (it + 1) / nk;
            int kc = ((it + 1) % nk) * 32;
            load_tiles(buf ^ 1, Aterm[t], Bterm[t], kc);
            CP_COMMIT();
        }
        uint32_t abase = as_base + buf * 8192;
        uint32_t bbase = bs_base + buf * 8192;
#pragma unroll
        for (int kk = 0; kk < 2; kk++) {
            uint32_t afr[4][4];
#pragma unroll
            for (int mi = 0; mi < 4; mi++) {
                int r = wm + mi * 16 + (lane & 15);
                int c = kk * 2 + (lane >> 4);
                uint32_t addr = abase + r * 64 + (uint32_t)((c ^ ((r >> 1) & 3)) * 16);
                LDSM_X4(afr[mi][0], afr[mi][1], afr[mi][2], afr[mi][3], addr);
            }
            uint32_t bfr[2][4];
#pragma unroll
            for (int nb = 0; nb < 2; nb++) {
                int r = wn + nb * 16 + (lane & 15);
                int c = kk * 2 + (lane >> 4);
                uint32_t addr = bbase + r * 64 + (uint32_t)((c ^ ((r >> 1) & 3)) * 16);
                LDSM_X4(bfr[nb][0], bfr[nb][1], bfr[nb][2], bfr[nb][3], addr);
            }
#pragma unroll
            for (int mi = 0; mi < 4; mi++)
#pragma unroll
                for (int nb = 0; nb < 2; nb++) {
                    MMA16816(acc[mi][nb * 2 + 0], afr[mi], bfr[nb][0], bfr[nb][2]);
                    MMA16816(acc[mi][nb * 2 + 1], afr[mi], bfr[nb][1], bfr[nb][3]);
                }
        }
        __syncthreads();
    }

    // epilogue
    int grow = row0 + wm;
    int gcol = col0 + wn;
#pragma unroll
    for (int mi = 0; mi < 4; mi++)
#pragma unroll
        for (int ni = 0; ni < 4; ni++) {
            int r  = grow + mi * 16 + (lane >> 2);
            int cc = gcol + ni * 8 + (lane & 3) * 2;
            float2 v0 = make_float2(acc[mi][ni][0], acc[mi][ni][1]);
            float2 v1 = make_float2(acc[mi][ni][2], acc[mi][ni][3]);
            if (bias) {
                float2 b2 = *(const float2*)(bias + cc);
                v0.x += b2.x; v0.y += b2.y;
                v1.x += b2.x; v1.y += b2.y;
            }
            if (resid) {
                float2 r0 = *(const float2*)(resid + (size_t)r * N + cc);
                float2 r1 = *(const float2*)(resid + (size_t)(r + 8) * N + cc);
                v0.x += r0.x; v0.y += r0.y;
                v1.x += r1.x; v1.y += r1.y;
            }
            if (CH) {
                __nv_bfloat16 h0, l0, h1, l1;
                split_hilo(v0.x, h0, l0); split_hilo(v0.y, h1, l1);
                *(uint32_t*)(CH + (size_t)r * N + cc) = pack_bf2(h0, h1);
                *(uint32_t*)(CL + (size_t)r * N + cc) = pack_bf2(l0, l1);
                split_hilo(v1.x, h0, l0); split_hilo(v1.y, h1, l1);
                *(uint32_t*)(CH + (size_t)(r + 8) * N + cc) = pack_bf2(h0, h1);
                *(uint32_t*)(CL + (size_t)(r + 8) * N + cc) = pack_bf2(l0, l1);
            } else {
                *(float2*)(C + (size_t)r * N + cc) = v0;
                *(float2*)(C + (size_t)(r + 8) * N + cc) = v1;
            }
        }
}

// ---------------- fp32 GEMM (small ctx projections only) ----------------
__global__ __launch_bounds__(256) void gemm_kernel(const float* __restrict__ A,
                                                   const float* __restrict__ B,
                                                   float* __restrict__ C,
                                                   int M, int N, int K) {
    __shared__ float As[16][128];
    __shared__ float Bs[16][128];
    int tid = threadIdx.x;
    int tx = tid & 15, ty = tid >> 4;
    int row0 = blockIdx.y * 128, col0 = blockIdx.x * 128;
    float acc[8][8];
#pragma unroll
    for (int i = 0; i < 8; i++)
#pragma unroll
        for (int j = 0; j < 8; j++) acc[i][j] = 0.f;

    for (int k0 = 0; k0 < K; k0 += 16) {
#pragma unroll
        for (int i = 0; i < 2; i++) {
            int idx = tid * 2 + i;
            int r = idx >> 2, kc = idx & 3;
            int gr = row0 + r;
            float4 f = make_float4(0.f, 0.f, 0.f, 0.f);
            if (gr < M) f = *(const float4*)(A + (size_t)gr * K + k0 + kc * 4);
            As[kc * 4 + 0][r] = f.x;
            As[kc * 4 + 1][r] = f.y;
            As[kc * 4 + 2][r] = f.z;
            As[kc * 4 + 3][r] = f.w;
        }
#pragma unroll
        for (int i = 0; i < 2; i++) {
            int idx = tid * 2 + i;
            int kb = idx >> 5, nc = idx & 31;
            float4 f = *(const float4*)(B + (size_t)(k0 + kb) * N + col0 + nc * 4);
            *(float4*)&Bs[kb][nc * 4] = f;
        }
        __syncthreads();
#pragma unroll
        for (int kk = 0; kk < 16; kk++) {
            float a[8], bb[8];
            *(float4*)&a[0]  = *(float4*)&As[kk][ty * 8];
            *(float4*)&a[4]  = *(float4*)&As[kk][ty * 8 + 4];
            *(float4*)&bb[0] = *(float4*)&Bs[kk][tx * 4];
            *(float4*)&bb[4] = *(float4*)&Bs[kk][64 + tx * 4];
#pragma unroll
            for (int i = 0; i < 8; i++)
#pragma unroll
                for (int j = 0; j < 8; j++) acc[i][j] += a[i] * bb[j];
        }
        __syncthreads();
    }
#pragma unroll
    for (int i = 0; i < 8; i++) {
        int gr = row0 + ty * 8 + i;
        if (gr >= M) continue;
#pragma unroll
        for (int half = 0; half < 2; half++) {
            int gc = col0 + half * 64 + tx * 4;
            float4 r4;
            r4.x = acc[i][half * 4 + 0];
            r4.y = acc[i][half * 4 + 1];
            r4.z = acc[i][half * 4 + 2];
            r4.w = acc[i][half * 4 + 3];
            *(float4*)(C + (size_t)gr * N + gc) = r4;
        }
    }
}

// ---------------- MMA flash attention ----------------
// 128 q rows/block, 64-kv tiles, 8 warps x 16 rows. bf16x3 for S and PV.
#define AQ_H 0
#define AQ_L 16384
#define AK_H 32768
#define AK_L 40960
#define AV_H 49152
#define AV_L 57344
#define ATT_SMEM 65536

__device__ __forceinline__ uint32_t att_sw(int r, int c) {  // 128B rows, chunk 0..7
    return (uint32_t)(r * 128 + ((c ^ (r & 7)) << 4));
}

__global__ __launch_bounds__(256) void attn_mma_kernel(
    const __nv_bfloat16* __restrict__ Qh, const __nv_bfloat16* __restrict__ Ql,
    const __nv_bfloat16* __restrict__ Kp_h, const __nv_bfloat16* __restrict__ Kp_l,
    const __nv_bfloat16* __restrict__ Vh, const __nv_bfloat16* __restrict__ Vl,
    __nv_bfloat16* __restrict__ Oh, __nv_bfloat16* __restrict__ Ol,
    int qlen, int kvlen)
{
    extern __shared__ char smc[];
    uint32_t sb = smem_to_u32(smc);
    int b = blockIdx.z, h = blockIdx.y, qt = blockIdx.x;
    int tid = threadIdx.x, warp = tid >> 5, lane = tid & 31;
    int qrow0 = qt * 128;
    size_t qbase  = ((size_t)b * qlen + qrow0) * DMODEL + h * DHEAD;
    size_t kvbase = ((size_t)b * kvlen) * DMODEL + h * DHEAD;

    // load 128x64 Q tile (hi+lo)
#pragma unroll
    for (int i = 0; i < 4; i++) {
        int idx = tid + i * 256;
        int r = idx >> 3, c = idx & 7;
        uint4 vh4 = *(const uint4*)(Qh + qbase + (size_t)r * DMODEL + c * 8);
        uint4 vl4 = *(const uint4*)(Ql + qbase + (size_t)r * DMODEL + c * 8);
        *(uint4*)(smc + AQ_H + att_sw(r, c)) = vh4;
        *(uint4*)(smc + AQ_L + att_sw(r, c)) = vl4;
    }
    __syncthreads();

    // cache per-warp Q fragments (4 k-chunks)
    uint32_t qfh[4][4], qfl[4][4];
    {
        int r = warp * 16 + (lane & 15);
#pragma unroll
        for (int kk = 0; kk < 4; kk++) {
            int c = kk * 2 + (lane >> 4);
            LDSM_X4(qfh[kk][0], qfh[kk][1], qfh[kk][2], qfh[kk][3], sb + AQ_H + att_sw(r, c));
            LDSM_X4(qfl[kk][0], qfl[kk][1], qfl[kk][2], qfl[kk][3], sb + AQ_L + att_sw(r, c));
        }
    }

    float m_a = -1e30f, m_b = -1e30f, l_a = 0.f, l_b = 0.f;
    float acc_o[8][4];
#pragma unroll
    for (int t = 0; t < 8; t++)
#pragma unroll
        for (int e = 0; e < 4; e++) acc_o[t][e] = 0.f;

    int ntiles = (kvlen + 63) >> 6;
    for (int kt = 0; kt < ntiles; kt++) {
        // fill K tile (64x64 hi/lo) zero-padded
#pragma unroll
        for (int i = 0; i < 2; i++) {
            int idx = tid + i * 256;
            int r = idx >> 3, c = idx & 7;
            int kr = kt * 64 + r;
            uint4 kh4 = make_uint4(0, 0, 0, 0), kl4 = kh4;
            if (kr < kvlen) {
                kh4 = *(const uint4*)(Kp_h + kvbase + (size_t)kr * DMODEL + c * 8);
                kl4 = *(const uint4*)(Kp_l + kvbase + (size_t)kr * DMODEL + c * 8);
            }
            *(uint4*)(smc + AK_H + att_sw(r, c)) = kh4;
            *(uint4*)(smc + AK_L + att_sw(r, c)) = kl4;
        }
        // fill Vt tile transposed: Vt[d][kv] (hi/lo) zero-padded
#pragma unroll
        for (int i = 0; i < 4; i++) {
            int idx = tid + i * 256;
            int r = idx >> 4, cg = idx & 15;
            int kr = kt * 64 + r;
            union { uint2 u; __nv_bfloat16 e[4]; } vhu, vlu;
            vhu.u = make_uint2(0, 0); vlu.u = make_uint2(0, 0);
            if (kr < kvlen) {
                vhu.u = *(const uint2*)(Vh + kvbase + (size_t)kr * DMODEL + cg * 4);
                vlu.u = *(const uint2*)(Vl + kvbase + (size_t)kr * DMODEL + cg * 4);
            }
#pragma unroll
            for (int j = 0; j < 4; j++) {
                int d = cg * 4 + j;
                uint32_t off = (uint32_t)(d * 128 + ((((r >> 3) ^ (d & 7))) << 4) + (r & 7) * 2);
                *(__nv_bfloat16*)(smc + AV_H + off) = vhu.e[j];
                *(__nv_bfloat16*)(smc + AV_L + off) = vlu.e[j];
            }
        }
        __syncthreads();

        // S = Q K^T (3-term)
        float s[8][4];
#pragma unroll
        for (int t = 0; t < 8; t++)
#pragma unroll
            for (int e = 0; e < 4; e++) s[t][e] = 0.f;
#pragma unroll
        for (int kk = 0; kk < 4; kk++) {
#pragma unroll
            for (int nq = 0; nq < 4; nq++) {
                int r = nq * 16 + (lane & 15);
                int c = kk * 2 + (lane >> 4);
                uint32_t khf[4], klf[4];
                LDSM_X4(khf[0], khf[1], khf[2], khf[3], sb + AK_H + att_sw(r, c));
                LDSM_X4(klf[0], klf[1], klf[2], klf[3], sb + AK_L + att_sw(r, c));
                MMA16816(s[nq * 2 + 0], qfh[kk], khf[0], khf[2]);
                MMA16816(s[nq * 2 + 1], qfh[kk], khf[1], khf[3]);
                MMA16816(s[nq * 2 + 0], qfh[kk], klf[0], klf[2]);
                MMA16816(s[nq * 2 + 1], qfh[kk], klf[1], klf[3]);
                MMA16816(s[nq * 2 + 0], qfl[kk], khf[0], khf[2]);
                MMA16816(s[nq * 2 + 1], qfl[kk], khf[1], khf[3]);
            }
        }
        // scale + mask
        bool mtile = (kt == ntiles - 1) && (kvlen & 63);
#pragma unroll
        for (int t = 0; t < 8; t++)
#pragma unroll
            for (int e = 0; e < 4; e++) {
                float vv = s[t][e] * 0.125f;
                if (mtile) {
                    int col = kt * 64 + t * 8 + (lane & 3) * 2 + (e & 1);
                    if (col >= kvlen) vv = -1e30f;
                }
                s[t][e] = vv;
            }
        // online softmax (rows: a = lane>>2, b = a+8)
        float mx_a = -1e30f, mx_b = -1e30f;
#pragma unroll
        for (int t = 0; t < 8; t++) {
            mx_a = fmaxf(mx_a, fmaxf(s[t][0], s[t][1]));
            mx_b = fmaxf(mx_b, fmaxf(s[t][2], s[t][3]));
        }
        mx_a = fmaxf(mx_a, __shfl_xor_sync(0xffffffffu, mx_a, 1));
        mx_a = fmaxf(mx_a, __shfl_xor_sync(0xffffffffu, mx_a, 2));
        mx_b = fmaxf(mx_b, __shfl_xor_sync(0xffffffffu, mx_b, 1));
        mx_b = fmaxf(mx_b, __shfl_xor_sync(0xffffffffu, mx_b, 2));
        float mn_a = fmaxf(m_a, mx_a), mn_b = fmaxf(m_b, mx_b);
        float al_a = __expf(m_a - mn_a), al_b = __expf(m_b - mn_b);
        m_a = mn_a; m_b = mn_b;
        float sum_a = 0.f, sum_b = 0.f;
#pragma unroll
        for (int t = 0; t < 8; t++) {
            s[t][0] = __expf(s[t][0] - m_a);
            s[t][1] = __expf(s[t][1] - m_a);
            s[t][2] = __expf(s[t][2] - m_b);
            s[t][3] = __expf(s[t][3] - m_b);
            sum_a += s[t][0] + s[t][1];
            sum_b += s[t][2] + s[t][3];
        }
        sum_a += __shfl_xor_sync(0xffffffffu, sum_a, 1);
        sum_a += __shfl_xor_sync(0xffffffffu, sum_a, 2);
        sum_b += __shfl_xor_sync(0xffffffffu, sum_b, 1);
        sum_b += __shfl_xor_sync(0xffffffffu, sum_b, 2);
        l_a = l_a * al_a + sum_a;
        l_b = l_b * al_b + sum_b;
#pragma unroll
        for (int t = 0; t < 8; t++) {
            acc_o[t][0] *= al_a; acc_o[t][1] *= al_a;
            acc_o[t][2] *= al_b; acc_o[t][3] *= al_b;
        }
        // PV (3-term), P fragments built from S fragments
#pragma unroll
        for (int kc = 0; kc < 4; kc++) {
            int t0 = kc * 2, t1 = t0 + 1;
            uint32_t pah[4], pal[4];
            {
                __nv_bfloat16 hb, lb, hb2, lb2;
                split_hilo(s[t0][0], hb, lb);  split_hilo(s[t0][1], hb2, lb2);
                pah[0] = pack_bf2(hb, hb2);    pal[0] = pack_bf2(lb, lb2);
                split_hilo(s[t0][2], hb, lb);  split_hilo(s[t0][3], hb2, lb2);
                pah[1] = pack_bf2(hb, hb2);    pal[1] = pack_bf2(lb, lb2);
                split_hilo(s[t1][0], hb, lb);  split_hilo(s[t1][1], hb2, lb2);
                pah[2] = pack_bf2(hb, hb2);    pal[2] = pack_bf2(lb, lb2);
                split_hilo(s[t1][2], hb, lb);  split_hilo(s[t1][3], hb2, lb2);
                pah[3] = pack_bf2(hb, hb2);    pal[3] = pack_bf2(lb, lb2);
            }
#pragma unroll
            for (int nd = 0; nd < 4; nd++) {
                int r = nd * 16 + (lane & 15);
                int c = kc * 2 + (lane >> 4);
                uint32_t vhf[4], vlf[4];
                LDSM_X4(vhf[0], vhf[1], vhf[2], vhf[3], sb + AV_H + att_sw(r, c));
                LDSM_X4(vlf[0], vlf[1], vlf[2], vlf[3], sb + AV_L + att_sw(r, c));
                MMA16816(acc_o[nd * 2 + 0], pah, vhf[0], vhf[2]);
                MMA16816(acc_o[nd * 2 + 1], pah, vhf[1], vhf[3]);
                MMA16816(acc_o[nd * 2 + 0], pah, vlf[0], vlf[2]);
                MMA16816(acc_o[nd * 2 + 1], pah, vlf[1], vlf[3]);
                MMA16816(acc_o[nd * 2 + 0], pal, vhf[0], vhf[2]);
                MMA16816(acc_o[nd * 2 + 1], pal, vhf[1], vhf[3]);
            }
        }
        __syncthreads();
    }

    // normalize + hi/lo store
    float inv_a = 1.0f / l_a, inv_b = 1.0f / l_b;
    int row_a = qrow0 + warp * 16 + (lane >> 2);
    size_t ob = ((size_t)b * qlen) * DMODEL + h * DHEAD;
#pragma unroll
    for (int nd = 0; nd < 8; nd++) {
        int d0 = nd * 8 + (lane & 3) * 2;
        float a0 = acc_o[nd][0] * inv_a, a1 = acc_o[nd][1] * inv_a;
        float b0 = acc_o[nd][2] * inv_b, b1 = acc_o[nd][3] * inv_b;
        __nv_bfloat16 h0, l0, h1, l1;
        split_hilo(a0, h0, l0); split_hilo(a1, h1, l1);
        *(uint32_t*)(Oh + ob + (size_t)row_a * DMODEL + d0) = pack_bf2(h0, h1);
        *(uint32_t*)(Ol + ob + (size_t)row_a * DMODEL + d0) = pack_bf2(l0, l1);
        split_hilo(b0, h0, l0); split_hilo(b1, h1, l1);
        *(uint32_t*)(Oh + ob + (size_t)(row_a + 8) * DMODEL + d0) = pack_bf2(h0, h1);
        *(uint32_t*)(Ol + ob + (size_t)(row_a + 8) * DMODEL + d0) = pack_bf2(l0, l1);
    }
}

// ---------------- GeGLU + hi/lo emit ----------------
__global__ __launch_bounds__(256) void geglu_hilo_kernel(const float* __restrict__ Hb,
                                                         __nv_bfloat16* __restrict__ Ho,
                                                         __nv_bfloat16* __restrict__ Lo) {
    int row = blockIdx.y;
    int c = (blockIdx.x * 256 + threadIdx.x) * 4;
    const float* hr = Hb + (size_t)row * FFH;
    float4 u = *(const float4*)(hr + c);
    float4 g = *(const float4*)(hr + FFHALF + c);
    const float k = 0.70710678118654752f;
    float r0 = u.x * (0.5f * g.x * (1.f + erff(g.x * k)));
    float r1 = u.y * (0.5f * g.y * (1.f + erff(g.y * k)));
    float r2 = u.z * (0.5f * g.z * (1.f + erff(g.z * k)));
    float r3 = u.w * (0.5f * g.w * (1.f + erff(g.w * k)));
    union { __nv_bfloat16 b[4]; uint2 uu; } ph, pl;
    split_hilo(r0, ph.b[0], pl.b[0]);
    split_hilo(r1, ph.b[1], pl.b[1]);
    split_hilo(r2, ph.b[2], pl.b[2]);
    split_hilo(r3, ph.b[3], pl.b[3]);
    size_t base = (size_t)row * FFHALF + c;
    *(uint2*)(Ho + base) = ph.uu;
    *(uint2*)(Lo + base) = pl.uu;
}

// ---------------- launch ----------------
extern "C" void kernel_launch(void* const* d_in, const int* in_sizes, int n_in,
                              void* d_out, int out_size) {
    const float* x    = (const float*)d_in[0];
    const float* ctx  = (const float*)d_in[1];
    const float* ln1g = (const float*)d_in[2];
    const float* ln1b = (const float*)d_in[3];
    const float* ln2g = (const float*)d_in[4];
    const float* ln2b = (const float*)d_in[5];
    const float* ln3g = (const float*)d_in[6];
    const float* ln3b = (const float*)d_in[7];
    const float* a1wq = (const float*)d_in[8];
    const float* a1wk = (const float*)d_in[9];
    const float* a1wv = (const float*)d_in[10];
    const float* a1wo = (const float*)d_in[11];
    const float* a1bo = (const float*)d_in[12];
    const float* a2wq = (const float*)d_in[13];
    const float* a2wk = (const float*)d_in[14];
    const float* a2wv = (const float*)d_in[15];
    const float* a2wo = (const float*)d_in[16];
    const float* a2bo = (const float*)d_in[17];
    const float* ffw1 = (const float*)d_in[18];
    const float* ffb1 = (const float*)d_in[19];
    const float* ffw2 = (const float*)d_in[20];
    const float* ffb2 = (const float*)d_in[21];
    float* out = (float*)d_out;

    float *xa, *hbuf, *ct1, *ct2;
    __nv_bfloat16 *ah, *al, *bh, *bl, *qh, *ql, *kh, *kl, *vh, *vl, *oh, *ol;
    cudaGetSymbolAddress((void**)&xa,   g_xa);
    cudaGetSymbolAddress((void**)&hbuf, g_h);
    cudaGetSymbolAddress((void**)&ct1,  g_ctmp1);
    cudaGetSymbolAddress((void**)&ct2,  g_ctmp2);
    cudaGetSymbolAddress((void**)&ah, g_ah);
    cudaGetSymbolAddress((void**)&al, g_al);
    cudaGetSymbolAddress((void**)&bh, g_bh);
    cudaGetSymbolAddress((void**)&bl, g_bl);
    cudaGetSymbolAddress((void**)&qh, g_qh);
    cudaGetSymbolAddress((void**)&ql, g_ql);
    cudaGetSymbolAddress((void**)&kh, g_kh);
    cudaGetSymbolAddress((void**)&kl, g_kl);
    cudaGetSymbolAddress((void**)&vh, g_vh);
    cudaGetSymbolAddress((void**)&vl, g_vl);
    cudaGetSymbolAddress((void**)&oh, g_oh);
    cudaGetSymbolAddress((void**)&ol, g_ol);

    cudaFuncSetAttribute(attn_mma_kernel, cudaFuncAttributeMaxDynamicSharedMemorySize, ATT_SMEM);

    dim3 blk(256);
    dim3 tblk(32, 8);
    dim3 tc1024(DMODEL / 128, MROWS / 128);
    dim3 tcFF1(FFH / 128, MROWS / 128);
    dim3 gemmCtx(DMODEL / 128, (CTXROWS + 127) / 128);
    dim3 attng(SEQ / 128, NHEAD, 4);
    dim3 tg1024(DMODEL / 32, DMODEL / 32);
    dim3 tgFF1(FFH / 32, DMODEL / 32);
    dim3 tgFF2(DMODEL / 32, FFHALF / 32);

    // --- self attention ---
    ln_hilo_kernel<<<MROWS, blk>>>(x, ln1g, ln1b, ah, al);
    tconv_kernel<<<tg1024, tblk>>>(a1wq, bh, bl, DMODEL, DMODEL);
    gemm_mma_kernel<<<tc1024, blk>>>(ah, al, bh, bl, nullptr, MROWS, DMODEL, DMODEL, nullptr, nullptr, qh, ql);
    tconv_kernel<<<tg1024, tblk>>>(a1wk, bh, bl, DMODEL, DMODEL);
    gemm_mma_kernel<<<tc1024, blk>>>(ah, al, bh, bl, nullptr, MROWS, DMODEL, DMODEL, nullptr, nullptr, kh, kl);
    tconv_kernel<<<tg1024, tblk>>>(a1wv, bh, bl, DMODEL, DMODEL);
    gemm_mma_kernel<<<tc1024, blk>>>(ah, al, bh, bl, nullptr, MROWS, DMODEL, DMODEL, nullptr, nullptr, vh, vl);
    attn_mma_kernel<<<attng, blk, ATT_SMEM>>>(qh, ql, kh, kl, vh, vl, oh, ol, SEQ, SEQ);
    tconv_kernel<<<tg1024, tblk>>>(a1wo, bh, bl, DMODEL, DMODEL);
    gemm_mma_kernel<<<tc1024, blk>>>(oh, ol, bh, bl, xa, MROWS, DMODEL, DMODEL, a1bo, x, nullptr, nullptr);

    // --- cross attention ---
    ln_hilo_kernel<<<MROWS, blk>>>(xa, ln2g, ln2b, ah, al);
    tconv_kernel<<<tg1024, tblk>>>(a2wq, bh, bl, DMODEL, DMODEL);
    gemm_mma_kernel<<<tc1024, blk>>>(ah, al, bh, bl, nullptr, MROWS, DMODEL, DMODEL, nullptr, nullptr, qh, ql);
    gemm_kernel<<<gemmCtx, blk>>>(ctx, a2wk, ct1, CTXROWS, DMODEL, CTXDIM);
    hilo_kernel<<<CTXROWS, blk>>>(ct1, kh, kl);
    gemm_kernel<<<gemmCtx, blk>>>(ctx, a2wv, ct2, CTXROWS, DMODEL, CTXDIM);
    hilo_kernel<<<CTXROWS, blk>>>(ct2, vh, vl);
    attn_mma_kernel<<<attng, blk, ATT_SMEM>>>(qh, ql, kh, kl, vh, vl, oh, ol, SEQ, CTXLEN);
    tconv_kernel<<<tg1024, tblk>>>(a2wo, bh, bl, DMODEL, DMODEL);
    gemm_mma_kernel<<<tc1024, blk>>>(oh, ol, bh, bl, xa, MROWS, DMODEL, DMODEL, a2bo, xa, nullptr, nullptr);

    // --- GeGLU feed-forward ---
    ln_hilo_kernel<<<MROWS, blk>>>(xa, ln3g, ln3b, ah, al);
    tconv_kernel<<<tgFF1, tblk>>>(ffw1, bh, bl, DMODEL, FFH);
    gemm_mma_kernel<<<tcFF1, blk>>>(ah, al, bh, bl, hbuf, MROWS, FFH, DMODEL, ffb1, nullptr, nullptr, nullptr);
    geglu_hilo_kernel<<<dim3(FFHALF / 1024, MROWS), blk>>>(hbuf, ah, al);
    tconv_kernel<<<tgFF2, tblk>>>(ffw2, bh, bl, FFHALF, DMODEL);
    gemm_mma_kernel<<<tc1024, blk>>>(ah, al, bh, bl, out, MROWS, DMODEL, FFHALF, ffb2, xa, nullptr, nullptr);
}